// round 14
// baseline (speedup 1.0000x reference)
#include <cuda_runtime.h>
#include <cuda_fp16.h>

// LODs = int(16*(256/16)^(L/7)) = 16,23,35,52,78,115,172,256
// entries: 256, 529, 1225, 2704, 6084, 13225, 29584, 65536
// LODs 0-6 in smem as scaled __half2 (53607*4B = 214.4KB); LOD7 in L2 (fp32).
//
// 16-point warp tile, 2 lanes/point: lane l = a*2+c (a = point, c = LOD-set).
//   c=0: LODs 0-3 (smem, both components)   c=1: LODs 4-7 (smem + cb7)
// Index math + table loads issued once per point (no x/y-lane duplication).
// 4x shfl.xor(1) butterfly assembles each lane's contiguous 32B output half
// (c=0 -> chunks {0,1} = x across all 8 LODs; c=1 -> chunks {2,3} = y),
// stored with one 256-bit st.global.cs.v8.f32 (warp-contiguous 1024B).

#define SMEM_H2 53607
#define SMEM_BYTES (SMEM_H2 * 4)
#define SD (1.0f / 1024.0f)
#define SU 1024.0f
#define TPB 1024

__device__ __forceinline__ void stg256(float* p,
                                       float r0, float r1, float r2, float r3,
                                       float r4, float r5, float r6, float r7)
{
    asm volatile("st.global.cs.v8.f32 [%0], {%1,%2,%3,%4,%5,%6,%7,%8};"
                 :: "l"(p), "f"(r0), "f"(r1), "f"(r2), "f"(r3),
                    "f"(r4), "f"(r5), "f"(r6), "f"(r7)
                 : "memory");
}

__global__ void __launch_bounds__(TPB, 1)
dense_grid_p16_kernel(const float2* __restrict__ pts,
                      const float2* __restrict__ cb0,
                      const float2* __restrict__ cb1,
                      const float2* __restrict__ cb2,
                      const float2* __restrict__ cb3,
                      const float2* __restrict__ cb4,
                      const float2* __restrict__ cb5,
                      const float2* __restrict__ cb6,
                      const float2* __restrict__ cb7,
                      float* __restrict__ out,
                      int n)
{
    extern __shared__ __half2 sh[];

    // ---- Stage LODs 0-6 into smem as scaled half2 (coalesced) ----
    {
        const float2* __restrict__ srcs[7] = {cb0, cb1, cb2, cb3, cb4, cb5, cb6};
        const int cnt[7] = {256, 529, 1225, 2704, 6084, 13225, 29584};
        const int off[7] = {0, 256, 785, 2010, 4714, 10798, 24023};
#pragma unroll
        for (int L = 0; L < 7; ++L) {
            const float2* src = srcs[L];
            __half2* dst = sh + off[L];
            const int cn = cnt[L];
            for (int j = threadIdx.x; j < cn; j += TPB) {
                const float2 v = __ldg(&src[j]);
                dst[j] = __floats2half2_rn(v.x * SU, v.y * SU);
            }
        }
    }
    __syncthreads();

    const int l = threadIdx.x & 31;
    const int c = l & 1;             // 0: LODs 0-3, 1: LODs 4-7
    const int a = l >> 1;            // point within the 16-point warp tile
    const bool hi = (c != 0);

    // Per-lane LOD-set constants (hoisted).
    const float sc0 = hi ? 77.0f : 15.0f;
    const float sc1 = hi ? 114.0f : 22.0f;
    const float sc2 = hi ? 171.0f : 34.0f;
    const float sc3 = hi ? 255.0f : 51.0f;
    const int r0 = hi ? 78 : 16;
    const int r1 = hi ? 115 : 23;
    const int r2 = hi ? 172 : 35;
    const int r3 = hi ? 256 : 52;
    const int o0 = hi ? 4714 : 0;
    const int o1 = hi ? 10798 : 256;
    const int o2 = hi ? 24023 : 785;
    const int o3 = 2010;             // LOD3 (lo path); hi path uses cb7

    // Each warp owns 16 consecutive points per iteration (n % 16 == 0).
    const int base0 = ((blockIdx.x * TPB + (threadIdx.x & ~31)) >> 1);
    const int stride = (gridDim.x * TPB) >> 1;   // points per sweep

    if (base0 >= n) return;

    // Prologue: point for the first iteration (2-way broadcast load).
    float2 p = __ldg(&pts[base0 + a]);

    for (int base = base0; base < n; base += stride) {
        // ---- Branch-free prefetch of next iteration's point ----
        const float2 pn = __ldg(&pts[min(base + stride + a, n - 1)]);

        const float px = p.x, py = p.y;
        // trunc == floor for nonneg; same single fp32 multiply as reference
        const int i0 = (int)(px * sc0) + (int)(py * sc0) * r0;
        const int i1 = (int)(px * sc1) + (int)(py * sc1) * r1;
        const int i2 = (int)(px * sc2) + (int)(py * sc2) * r2;
        const int i3 = (int)(px * sc3) + (int)(py * sc3) * r3;

        // Last LOD of this lane's set: cb7 (global fp32) for hi, smem for lo.
        float2 e3;
        if (hi) {
            e3 = __ldg(&cb7[i3]);
        } else {
            const float2 t = __half22float2(sh[o3 + i3]);
            e3 = make_float2(t.x * SD, t.y * SD);
        }

        const float2 t0 = __half22float2(sh[o0 + i0]);
        const float2 t1 = __half22float2(sh[o1 + i1]);
        const float2 t2 = __half22float2(sh[o2 + i2]);

        const float X0 = t0.x * SD, X1 = t1.x * SD, X2 = t2.x * SD, X3 = e3.x;
        const float Y0 = t0.y * SD, Y1 = t1.y * SD, Y2 = t2.y * SD, Y3 = e3.y;

        // Butterfly with partner lane (c^1): send Y if c==0 else X.
        const float s0 = hi ? X0 : Y0;
        const float s1 = hi ? X1 : Y1;
        const float s2 = hi ? X2 : Y2;
        const float s3 = hi ? X3 : Y3;
        const float q0 = __shfl_xor_sync(0xffffffffu, s0, 1);
        const float q1 = __shfl_xor_sync(0xffffffffu, s1, 1);
        const float q2 = __shfl_xor_sync(0xffffffffu, s2, 1);
        const float q3 = __shfl_xor_sync(0xffffffffu, s3, 1);
        // c=0 received partner's X4-7 -> holds chunks {0,1} = x of LODs 0-7.
        // c=1 received partner's Y0-3 -> holds chunks {2,3} = y of LODs 0-7.
        const float r0f = hi ? q0 : X0;
        const float r1f = hi ? q1 : X1;
        const float r2f = hi ? q2 : X2;
        const float r3f = hi ? q3 : X3;
        const float r4f = hi ? Y0 : q0;
        const float r5f = hi ? Y1 : q1;
        const float r6f = hi ? Y2 : q2;
        const float r7f = hi ? Y3 : q3;

        // One 256-bit store per lane; warp covers 1024B contiguous.
        stg256(out + (size_t)base * 16 + (size_t)l * 8,
               r0f, r1f, r2f, r3f, r4f, r5f, r6f, r7f);

        p = pn;
    }
}

extern "C" void kernel_launch(void* const* d_in, const int* in_sizes, int n_in,
                              void* d_out, int out_size)
{
    const float2* pts = (const float2*)d_in[0];
    const float2* cb0 = (const float2*)d_in[1];
    const float2* cb1 = (const float2*)d_in[2];
    const float2* cb2 = (const float2*)d_in[3];
    const float2* cb3 = (const float2*)d_in[4];
    const float2* cb4 = (const float2*)d_in[5];
    const float2* cb5 = (const float2*)d_in[6];
    const float2* cb6 = (const float2*)d_in[7];
    const float2* cb7 = (const float2*)d_in[8];
    float* out = (float*)d_out;

    const int n = in_sizes[0] / 2;

    static int sm_count = -1;
    if (sm_count < 0) {
        cudaFuncSetAttribute(dense_grid_p16_kernel,
                             cudaFuncAttributeMaxDynamicSharedMemorySize,
                             SMEM_BYTES);
        cudaDeviceGetAttribute(&sm_count, cudaDevAttrMultiProcessorCount, 0);
    }

    dense_grid_p16_kernel<<<sm_count, TPB, SMEM_BYTES>>>(
        pts, cb0, cb1, cb2, cb3, cb4, cb5, cb6, cb7, out, n);
}

// round 15
// speedup vs baseline: 1.1045x; 1.1045x over previous
#include <cuda_runtime.h>
#include <cuda_fp16.h>

// LODs = int(16*(256/16)^(L/7)) = 16,23,35,52,78,115,172,256
// entries: 256, 529, 1225, 2704, 6084, 13225, 29584, 65536
// LODs 0-6 pre-converted ONCE (prep kernel) to scaled fp16 in __device__
// scratch (53607 half2 words, padded to 53608 for uint4 copies); the main
// kernel stages them into smem with plain uint4 copies (no conversion, half
// the L2 bytes of the fp32 path). LOD7 stays fp32 in L2.
//
// Main loop = best-known shape (R11): 8-point warp tile, chunk-per-lane
// (lane l = a*4+c handles chunk c of point base+a), no shuffles, one
// coalesced STG.128 per lane, branch-free clamped pts prefetch.
// Scale-down uses packed mul.rn.f32x2 (1 instr per table entry pair).
//   chunk 0: x of LODs0-3   chunk 1: x of LODs4-7
//   chunk 2: y of LODs0-3   chunk 3: y of LODs4-7

#define TAB_W   53607
#define TAB_PAD 53608
#define SMEM_BYTES (TAB_PAD * 4)
#define SD (1.0f / 1024.0f)
#define SU 1024.0f
#define TPB 1024

__device__ unsigned g_tab[TAB_PAD];

// ---- packed f32x2 scale-down: one mul.rn.f32x2 for both components ----
__device__ __forceinline__ float2 h2_to_f2_scaled(const __half2 h)
{
    const float2 v = __half22float2(h);
    unsigned long long a, r;
    asm("mov.b64 %0, {%1, %2};" : "=l"(a) : "f"(v.x), "f"(v.y));
    const unsigned long long sdp =
        ((unsigned long long)__float_as_uint(SD) << 32) | __float_as_uint(SD);
    asm("mul.rn.f32x2 %0, %1, %2;" : "=l"(r) : "l"(a), "l"(sdp));
    float2 o;
    asm("mov.b64 {%0, %1}, %2;" : "=f"(o.x), "=f"(o.y) : "l"(r));
    return o;
}

// ---- Prep kernel: convert LODs 0-6 fp32 -> scaled half2 scratch (once) ----
__global__ void prep_tables_kernel(const float2* __restrict__ cb0,
                                   const float2* __restrict__ cb1,
                                   const float2* __restrict__ cb2,
                                   const float2* __restrict__ cb3,
                                   const float2* __restrict__ cb4,
                                   const float2* __restrict__ cb5,
                                   const float2* __restrict__ cb6)
{
    const int j = blockIdx.x * blockDim.x + threadIdx.x;
    if (j >= TAB_PAD) return;
    if (j >= TAB_W) { g_tab[j] = 0u; return; }

    // segment offsets: 0,256,785,2010,4714,10798,24023
    const float2* src;
    int k;
    if (j < 4714) {
        if (j < 785) {
            if (j < 256) { src = cb0; k = j; }
            else         { src = cb1; k = j - 256; }
        } else {
            if (j < 2010) { src = cb2; k = j - 785; }
            else          { src = cb3; k = j - 2010; }
        }
    } else {
        if (j < 24023) {
            if (j < 10798) { src = cb4; k = j - 4714; }
            else           { src = cb5; k = j - 10798; }
        } else { src = cb6; k = j - 24023; }
    }
    const float2 v = __ldg(&src[k]);
    const __half2 h = __floats2half2_rn(v.x * SU, v.y * SU);
    g_tab[j] = *(const unsigned*)&h;
}

__global__ void __launch_bounds__(TPB, 1)
dense_grid_main_kernel(const float2* __restrict__ pts,
                       const float2* __restrict__ cb7,
                       float4* __restrict__ out,
                       int n)
{
    extern __shared__ unsigned sw[];
    const __half2* sh = (const __half2*)sw;

    // ---- Stage scratch -> smem with uint4 copies (no conversion) ----
    {
        const uint4* src = (const uint4*)g_tab;
        uint4* dst = (uint4*)sw;
        for (int j = threadIdx.x; j < TAB_PAD / 4; j += TPB)
            dst[j] = __ldg(&src[j]);
    }
    __syncthreads();

    const int l = threadIdx.x & 31;
    const int c = l & 3;
    const bool odd = (c & 1);        // odd chunk -> LODs 4-7
    const bool ycomp = (c & 2) != 0; // high chunk -> y component
    const int a = l >> 2;

    // Per-lane LOD-set constants (hoisted).
    const float sc0 = odd ? 77.0f : 15.0f;
    const float sc1 = odd ? 114.0f : 22.0f;
    const float sc2 = odd ? 171.0f : 34.0f;
    const float sc3 = odd ? 255.0f : 51.0f;
    const int r0 = odd ? 78 : 16;
    const int r1 = odd ? 115 : 23;
    const int r2 = odd ? 172 : 35;
    const int r3 = odd ? 256 : 52;
    const int o0 = odd ? 4714 : 0;
    const int o1 = odd ? 10798 : 256;
    const int o2 = odd ? 24023 : 785;
    const int o3 = 2010;             // LOD3 (even path); odd path uses cb7

    // Each warp owns 8 consecutive points per iteration (n % 8 == 0).
    const int base0 = ((blockIdx.x * TPB + (threadIdx.x & ~31)) >> 2);
    const int stride = (gridDim.x * TPB) >> 2;   // points per sweep

    if (base0 >= n) return;

    // Prologue: point for the first iteration.
    float2 p = __ldg(&pts[base0 + a]);

    for (int base = base0; base < n; base += stride) {
        // ---- Branch-free prefetch of next iteration's point ----
        const float2 pn = __ldg(&pts[min(base + stride + a, n - 1)]);

        // ---- Current iteration (p already resident) ----
        const float px = p.x, py = p.y;
        // trunc == floor for nonneg; same single fp32 multiply as reference
        const int i0 = (int)(px * sc0) + (int)(py * sc0) * r0;
        const int i1 = (int)(px * sc1) + (int)(py * sc1) * r1;
        const int i2 = (int)(px * sc2) + (int)(py * sc2) * r2;
        const int i3 = (int)(px * sc3) + (int)(py * sc3) * r3;

        // Last element: LOD7 (global fp32, L2-resident) for odd chunks.
        float2 g;
        if (odd) {
            g = __ldg(&cb7[i3]);
        } else {
            g = h2_to_f2_scaled(sh[o3 + i3]);
        }

        const float2 v0 = h2_to_f2_scaled(sh[o0 + i0]);
        const float2 v1 = h2_to_f2_scaled(sh[o1 + i1]);
        const float2 v2 = h2_to_f2_scaled(sh[o2 + i2]);

        float4 w;
        if (ycomp)
            w = make_float4(v0.y, v1.y, v2.y, g.y);
        else
            w = make_float4(v0.x, v1.x, v2.x, g.x);

        // Fully coalesced streaming store (output is write-once).
        __stcs(&out[(size_t)base * 4 + l], w);

        p = pn;
    }
}

extern "C" void kernel_launch(void* const* d_in, const int* in_sizes, int n_in,
                              void* d_out, int out_size)
{
    const float2* pts = (const float2*)d_in[0];
    const float2* cb0 = (const float2*)d_in[1];
    const float2* cb1 = (const float2*)d_in[2];
    const float2* cb2 = (const float2*)d_in[3];
    const float2* cb3 = (const float2*)d_in[4];
    const float2* cb4 = (const float2*)d_in[5];
    const float2* cb5 = (const float2*)d_in[6];
    const float2* cb6 = (const float2*)d_in[7];
    const float2* cb7 = (const float2*)d_in[8];
    float4* out = (float4*)d_out;

    const int n = in_sizes[0] / 2;

    static int sm_count = -1;
    if (sm_count < 0) {
        cudaFuncSetAttribute(dense_grid_main_kernel,
                             cudaFuncAttributeMaxDynamicSharedMemorySize,
                             SMEM_BYTES);
        cudaDeviceGetAttribute(&sm_count, cudaDevAttrMultiProcessorCount, 0);
    }

    // 1) Convert small-LOD tables to scaled fp16 scratch (tiny).
    prep_tables_kernel<<<(TAB_PAD + 255) / 256, 256>>>(cb0, cb1, cb2, cb3,
                                                       cb4, cb5, cb6);
    // 2) Main persistent kernel.
    dense_grid_main_kernel<<<sm_count, TPB, SMEM_BYTES>>>(pts, cb7, out, n);
}

// round 16
// speedup vs baseline: 1.1338x; 1.0265x over previous
#include <cuda_runtime.h>
#include <cuda_fp16.h>

// LODs = int(16*(256/16)^(L/7)) = 16,23,35,52,78,115,172,256
// entries: 256, 529, 1225, 2704, 6084, 13225, 29584, 65536
// LODs 0-6 in smem as scaled __half2 (53607*4B = 214.4KB); LOD7 in L2 (fp32).
//
// Best-known shape (R11): 8-point warp tile, chunk-per-lane (lane l = a*4+c
// handles chunk c of point base+a), no shuffles, one coalesced STG.128 per
// lane, branch-free clamped pts prefetch. This round: single kernel, packed
// mul.rn.f32x2 scale-down, and first-iteration pts/cb7 loads issued under
// the staging phase so the loop starts with resident data.
//   chunk 0: x of LODs0-3   chunk 1: x of LODs4-7
//   chunk 2: y of LODs0-3   chunk 3: y of LODs4-7

#define SMEM_H2 53607
#define SMEM_BYTES (SMEM_H2 * 4)
#define SD (1.0f / 1024.0f)
#define SU 1024.0f
#define TPB 1024

// packed f32x2 scale-down: one mul.rn.f32x2 for both components
__device__ __forceinline__ float2 h2_to_f2_scaled(const __half2 h)
{
    const float2 v = __half22float2(h);
    unsigned long long a, r;
    asm("mov.b64 %0, {%1, %2};" : "=l"(a) : "f"(v.x), "f"(v.y));
    const unsigned long long sdp =
        ((unsigned long long)__float_as_uint(SD) << 32) | __float_as_uint(SD);
    asm("mul.rn.f32x2 %0, %1, %2;" : "=l"(r) : "l"(a), "l"(sdp));
    float2 o;
    asm("mov.b64 {%0, %1}, %2;" : "=f"(o.x), "=f"(o.y) : "l"(r));
    return o;
}

__global__ void __launch_bounds__(TPB, 1)
dense_grid_r15_kernel(const float2* __restrict__ pts,
                      const float2* __restrict__ cb0,
                      const float2* __restrict__ cb1,
                      const float2* __restrict__ cb2,
                      const float2* __restrict__ cb3,
                      const float2* __restrict__ cb4,
                      const float2* __restrict__ cb5,
                      const float2* __restrict__ cb6,
                      const float2* __restrict__ cb7,
                      float4* __restrict__ out,
                      int n)
{
    extern __shared__ __half2 sh[];

    const int l = threadIdx.x & 31;
    const int c = l & 3;
    const bool odd = (c & 1);        // odd chunk -> LODs 4-7
    const bool ycomp = (c & 2) != 0; // high chunk -> y component
    const int a = l >> 2;

    // Each warp owns 8 consecutive points per iteration (n % 8 == 0).
    const int base0 = ((blockIdx.x * TPB + (threadIdx.x & ~31)) >> 2);
    const int stride = (gridDim.x * TPB) >> 2;   // points per sweep

    // Issue the first iteration's point load BEFORE staging so its DRAM
    // latency is hidden under the ~10K-cycle staging phase.
    float2 p = make_float2(0.f, 0.f);
    const bool active = (base0 < n);
    if (active) p = __ldg(&pts[base0 + a]);

    // ---- Stage LODs 0-6 into smem as scaled half2 (coalesced) ----
    {
        const float2* __restrict__ srcs[7] = {cb0, cb1, cb2, cb3, cb4, cb5, cb6};
        const int cnt[7] = {256, 529, 1225, 2704, 6084, 13225, 29584};
        const int off[7] = {0, 256, 785, 2010, 4714, 10798, 24023};
#pragma unroll
        for (int L = 0; L < 7; ++L) {
            const float2* src = srcs[L];
            __half2* dst = sh + off[L];
            const int cn = cnt[L];
            for (int j = threadIdx.x; j < cn; j += TPB) {
                const float2 v = __ldg(&src[j]);
                dst[j] = __floats2half2_rn(v.x * SU, v.y * SU);
            }
        }
    }

    // Per-lane LOD-set constants (hoisted).
    const float sc0 = odd ? 77.0f : 15.0f;
    const float sc1 = odd ? 114.0f : 22.0f;
    const float sc2 = odd ? 171.0f : 34.0f;
    const float sc3 = odd ? 255.0f : 51.0f;
    const int r0 = odd ? 78 : 16;
    const int r1 = odd ? 115 : 23;
    const int r2 = odd ? 172 : 35;
    const int r3 = odd ? 256 : 52;
    const int o0 = odd ? 4714 : 0;
    const int o1 = odd ? 10798 : 256;
    const int o2 = odd ? 24023 : 785;
    const int o3 = 2010;             // LOD3 (even path); odd path uses cb7

    // First iteration's cb7 gather (does not touch smem) issued pre-sync.
    float2 g7f = make_float2(0.f, 0.f);
    if (active && odd) {
        const int i3f = (int)(p.x * sc3) + (int)(p.y * sc3) * r3;
        g7f = __ldg(&cb7[i3f]);
    }

    __syncthreads();

    if (!active) return;

    bool first = true;
    for (int base = base0; base < n; base += stride) {
        // ---- Branch-free prefetch of next iteration's point ----
        const float2 pn = __ldg(&pts[min(base + stride + a, n - 1)]);

        // ---- Current iteration (p already resident) ----
        const float px = p.x, py = p.y;
        // trunc == floor for nonneg; same single fp32 multiply as reference
        const int i0 = (int)(px * sc0) + (int)(py * sc0) * r0;
        const int i1 = (int)(px * sc1) + (int)(py * sc1) * r1;
        const int i2 = (int)(px * sc2) + (int)(py * sc2) * r2;
        const int i3 = (int)(px * sc3) + (int)(py * sc3) * r3;

        // Last element: LOD7 (global fp32, L2-resident) for odd chunks.
        float2 g;
        if (odd) {
            g = first ? g7f : __ldg(&cb7[i3]);
        } else {
            g = h2_to_f2_scaled(sh[o3 + i3]);
        }
        first = false;

        const float2 v0 = h2_to_f2_scaled(sh[o0 + i0]);
        const float2 v1 = h2_to_f2_scaled(sh[o1 + i1]);
        const float2 v2 = h2_to_f2_scaled(sh[o2 + i2]);

        float4 w;
        if (ycomp)
            w = make_float4(v0.y, v1.y, v2.y, g.y);
        else
            w = make_float4(v0.x, v1.x, v2.x, g.x);

        // Fully coalesced streaming store (output is write-once).
        __stcs(&out[(size_t)base * 4 + l], w);

        p = pn;
    }
}

extern "C" void kernel_launch(void* const* d_in, const int* in_sizes, int n_in,
                              void* d_out, int out_size)
{
    const float2* pts = (const float2*)d_in[0];
    const float2* cb0 = (const float2*)d_in[1];
    const float2* cb1 = (const float2*)d_in[2];
    const float2* cb2 = (const float2*)d_in[3];
    const float2* cb3 = (const float2*)d_in[4];
    const float2* cb4 = (const float2*)d_in[5];
    const float2* cb5 = (const float2*)d_in[6];
    const float2* cb6 = (const float2*)d_in[7];
    const float2* cb7 = (const float2*)d_in[8];
    float4* out = (float4*)d_out;

    const int n = in_sizes[0] / 2;

    static int sm_count = -1;
    if (sm_count < 0) {
        cudaFuncSetAttribute(dense_grid_r15_kernel,
                             cudaFuncAttributeMaxDynamicSharedMemorySize,
                             SMEM_BYTES);
        cudaDeviceGetAttribute(&sm_count, cudaDevAttrMultiProcessorCount, 0);
    }

    dense_grid_r15_kernel<<<sm_count, TPB, SMEM_BYTES>>>(
        pts, cb0, cb1, cb2, cb3, cb4, cb5, cb6, cb7, out, n);
}